// round 16
// baseline (speedup 1.0000x reference)
#include <cuda_runtime.h>
#include <cuda_bf16.h>
#include <cstdint>
#include <math.h>

// Inputs: [0] if1 [4096,256] f32, [1] if2, [2] scale [1], [3] mb1 [16384,256] f32 (unit rows), [4] mb2
// Output: scalar f32.

namespace {
constexpr int NB = 4096, NC = 256, NM = 16384;
constexpr int TM = 128, TN = 128;
constexpr int ROWB = 512;             // bytes per K-major bf16 row
constexpr int TILEB = TM * ROWB;      // 64 KB
constexpr int NCH = 40;               // 512-col chunks over 20480
constexpr int NUNITS = 2 * 32 * NCH;  // 2560 uniform units of 4 tiles
constexpr int NTHREADS = 512;         // 16 warps, 4 per SMSP
constexpr int SMEM_DYN = 1024 + 3 * TILEB + 4096;  // pad + A + B0 + B1 + scratch
}

// Device-global scratch (no allocations allowed)
__device__ __nv_bfloat16 g_f1h[NB * NC];
__device__ __nv_bfloat16 g_f2h[NB * NC];
__device__ __nv_bfloat16 g_mb1h[NM * NC];
__device__ __nv_bfloat16 g_mb2h[NM * NC];
__device__ float g_s[2][NB][NCH];
__device__ float g_bmax[2][NB][NCH];
__device__ float g_diag[2][NB];
__device__ float g_part[32][8];       // per-block partials (5 used)
__device__ int   g_cnt;               // krow completion counter (self-resetting)

// ---------------- PTX helpers (plain sm_80+-class) ----------------
__device__ __forceinline__ uint32_t smem_u32(const void* p) {
    uint32_t a;
    asm("{ .reg .u64 t; cvta.to.shared.u64 t, %1; cvt.u32.u64 %0, t; }" : "=r"(a) : "l"(p));
    return a;
}
__device__ __forceinline__ void cp16(uint32_t d, const void* s) {
    asm volatile("cp.async.cg.shared.global [%0], [%1], 16;" :: "r"(d), "l"(s) : "memory");
}
__device__ __forceinline__ void cp_commit() { asm volatile("cp.async.commit_group;" ::: "memory"); }
__device__ __forceinline__ void cp_wait0()  { asm volatile("cp.async.wait_group 0;" ::: "memory"); }
__device__ __forceinline__ void ldsm4(uint32_t& r0, uint32_t& r1, uint32_t& r2, uint32_t& r3,
                                      uint32_t addr) {
    asm volatile("ldmatrix.sync.aligned.m8n8.x4.shared.b16 {%0,%1,%2,%3}, [%4];"
                 : "=r"(r0), "=r"(r1), "=r"(r2), "=r"(r3) : "r"(addr));
}
__device__ __forceinline__ void mma16816(float* c, const uint32_t* a, const uint32_t* b) {
    asm volatile(
        "mma.sync.aligned.m16n8k16.row.col.f32.bf16.bf16.f32 "
        "{%0,%1,%2,%3}, {%4,%5,%6,%7}, {%8,%9}, {%0,%1,%2,%3};"
        : "+f"(c[0]), "+f"(c[1]), "+f"(c[2]), "+f"(c[3])
        : "r"(a[0]), "r"(a[1]), "r"(a[2]), "r"(a[3]), "r"(b[0]), "r"(b[1]));
}
__device__ __forceinline__ float ex2f(float x) {
    float e; asm("ex2.approx.f32 %0, %1;" : "=f"(e) : "f"(x)); return e;
}

// ---------------------------------------------------------------------------
// Prep: normalize features -> bf16; convert banks -> bf16. One warp per row.
// (Measured near bandwidth-bound: 60 MB total traffic, ~86% of achievable.)
// ---------------------------------------------------------------------------
__global__ void kprep(const float* __restrict__ in1, const float* __restrict__ in2,
                      const float* __restrict__ b1, const float* __restrict__ b2) {
    int gw = (blockIdx.x * blockDim.x + threadIdx.x) >> 5;
    int lane = threadIdx.x & 31;
    const float* src; __nv_bfloat16* dst; bool donorm; int row;
    if (gw < NB)               { src = in1; dst = g_f1h;  row = gw;               donorm = true; }
    else if (gw < 2 * NB)      { src = in2; dst = g_f2h;  row = gw - NB;          donorm = true; }
    else if (gw < 2 * NB + NM) { src = b1;  dst = g_mb1h; row = gw - 2 * NB;      donorm = false; }
    else                       { src = b2;  dst = g_mb2h; row = gw - 2 * NB - NM; donorm = false; }

    const float4* s4 = (const float4*)(src + (size_t)row * NC);
    float4 v0 = s4[lane * 2], v1 = s4[lane * 2 + 1];
    float inv = 1.0f;
    if (donorm) {
        float ss = v0.x*v0.x + v0.y*v0.y + v0.z*v0.z + v0.w*v0.w
                 + v1.x*v1.x + v1.y*v1.y + v1.z*v1.z + v1.w*v1.w;
        #pragma unroll
        for (int o = 16; o > 0; o >>= 1) ss += __shfl_xor_sync(0xffffffffu, ss, o);
        inv = 1.0f / fmaxf(sqrtf(ss), 1e-12f);
    }
    __nv_bfloat162 p0 = __floats2bfloat162_rn(v0.x * inv, v0.y * inv);
    __nv_bfloat162 p1 = __floats2bfloat162_rn(v0.z * inv, v0.w * inv);
    __nv_bfloat162 p2 = __floats2bfloat162_rn(v1.x * inv, v1.y * inv);
    __nv_bfloat162 p3 = __floats2bfloat162_rn(v1.z * inv, v1.w * inv);
    uint4 o;
    o.x = *(uint32_t*)&p0; o.y = *(uint32_t*)&p1; o.z = *(uint32_t*)&p2; o.w = *(uint32_t*)&p3;
    ((uint4*)(dst + (size_t)row * NC))[lane] = o;
}

// ---------------------------------------------------------------------------
// Persistent fused GEMM (mma.sync bf16), 16 warps, warp tile 32x32.
// Unit = (dir, rowt, 512-col chunk) = 4 tiles. Static contiguous partition.
// Deferred epilogue via c0/c1 accumulator double-buffer: prev tile's
// exp-sum/max/diag interleaves with current tile's MMA loop (2 elems per ks).
// ---------------------------------------------------------------------------
#define TILE_BODY(CCUR, CPREV, TT, DOPREV, PREFETCH_STMT)                          \
  {                                                                                \
    cp_wait0(); __syncthreads();                                                   \
    PREFETCH_STMT                                                                  \
    _Pragma("unroll") for (int mf = 0; mf < 2; mf++)                               \
      _Pragma("unroll") for (int nf = 0; nf < 4; nf++)                             \
        _Pragma("unroll") for (int e = 0; e < 4; e++) CCUR[mf][nf][e] = 0.0f;      \
    const uint32_t bA0 = (pb ? bBuf1 : bBuf0) + (uint32_t)bRowL * ROWB;            \
    const uint32_t bA1 = bA0 + 16u * ROWB;                                         \
    const int pcolg0 = chunk * 512 + ((TT) - 1) * 128;                             \
    const int pBank = pcolg0 >= NB;                                                \
    const int pDiag = (!pBank) && (pcolg0 == rowt * 128);                          \
    _Pragma("unroll") for (int ks = 0; ks < 16; ks++) {                            \
      const uint32_t offA = ((uint32_t)(ks * 32) + aKsel) ^ sw;                    \
      const uint32_t offB = ((uint32_t)(ks * 32) + bKsel) ^ sw;                    \
      uint32_t a[2][4], b[4][2];                                                   \
      ldsm4(a[0][0], a[0][1], a[0][2], a[0][3], aAddr0 + offA);                    \
      ldsm4(a[1][0], a[1][1], a[1][2], a[1][3], aAddr1 + offA);                    \
      ldsm4(b[0][0], b[0][1], b[1][0], b[1][1], bA0 + offB);                       \
      ldsm4(b[2][0], b[2][1], b[3][0], b[3][1], bA1 + offB);                       \
      _Pragma("unroll") for (int mf = 0; mf < 2; mf++)                             \
        _Pragma("unroll") for (int nf = 0; nf < 4; nf++)                           \
          mma16816(CCUR[mf][nf], a[mf], b[nf]);                                    \
      if (DOPREV) {                                                                \
        const int mf = ks & 1, nf = (ks >> 1) & 3, eh = ks >> 3;                   \
        _Pragma("unroll") for (int e2 = 0; e2 < 2; e2++) {                         \
          const int e = eh * 2 + e2;                                               \
          float v = CPREV[mf][nf][e];                                              \
          int ri = mf * 2 + eh;                                                    \
          s_acc[ri] += ex2f(fmaf(cl2, v, -cl2));                                   \
          if (pBank) bmax[ri] = fmaxf(bmax[ri], v);                                \
          else if (pDiag) {                                                        \
            int row_l = wm * 32 + mf * 16 + (lane >> 2) + 8 * eh;                  \
            int col_l = wn * 32 + nf * 8 + 2 * (lane & 3) + e2;                    \
            if (row_l == col_l) g_diag[dir][rowt * 128 + row_l] = scale * v;       \
          }                                                                        \
        }                                                                          \
      }                                                                            \
    }                                                                              \
    pb ^= 1;                                                                       \
  }

__global__ void __launch_bounds__(NTHREADS, 1) kgemm(const float* __restrict__ scale_ptr) {
    extern __shared__ char dsm[];
    const uint32_t raw  = smem_u32(dsm);
    const uint32_t base = (raw + 1023u) & ~1023u;
    const uint32_t aBase = base;
    const uint32_t bBuf0 = base + TILEB;
    const uint32_t bBuf1 = base + 2 * TILEB;
    float* scrS = (float*)(dsm + (base - raw) + 3 * TILEB);
    float* scrM = scrS + 512;

    const int tid = threadIdx.x, wid = tid >> 5, lane = tid & 31;
    const int wm = wid & 3, wn = wid >> 2;        // 4x4 warp grid, 32x32 tiles
    const float scale = *scale_ptr;
    const float cl2 = scale * 1.4426950408889634f;

    const int G = gridDim.x;
    int uBeg = (int)((long long)blockIdx.x * NUNITS / G);
    int uEnd = (int)((long long)(blockIdx.x + 1) * NUNITS / G);
    if (uBeg >= uEnd) return;

    const int r8 = lane & 7;
    const uint32_t sw = (uint32_t)(r8 << 4);
    const int aRowL = wm * 32 + r8 + ((lane >> 3) & 1) * 8;
    const uint32_t aKsel = (uint32_t)(((lane >> 4) & 1) * 16);
    const int bRowL = wn * 32 + r8 + ((lane >> 4) & 1) * 8;
    const uint32_t bKsel = (uint32_t)(((lane >> 3) & 1) * 16);
    const uint32_t aAddr0 = aBase + (uint32_t)aRowL * ROWB;
    const uint32_t aAddr1 = aAddr0 + 16u * ROWB;

    auto loadTile = [&](uint32_t sb, const char* src) {
        #pragma unroll
        for (int it = 0; it < 8; it++) {
            int idx = tid + it * NTHREADS;
            int r   = idx >> 5;
            uint32_t kb = (uint32_t)((idx & 31) * 16);
            cp16(sb + (uint32_t)r * ROWB + (kb ^ (uint32_t)((r & 7) << 4)),
                 src + (size_t)r * ROWB + kb);
        }
    };
    auto aSrcP = [&](int d, int rt) -> const char* {
        return (const char*)((d ? g_f2h : g_f1h) + (size_t)rt * TM * NC);
    };
    auto bSrcP = [&](int d, int ch, int t) -> const char* {
        int colg0 = ch * 512 + t * 128;
        const __nv_bfloat16* p = (colg0 < NB)
            ? (d ? g_f1h : g_f2h) + (size_t)colg0 * NC
            : (d ? g_mb1h : g_mb2h) + (size_t)(colg0 - NB) * NC;
        return (const char*)p;
    };

    int u = uBeg;
    int dir = u / 1280, rem = u % 1280, rowt = rem / 40, chunk = rem % 40;
    loadTile(aBase, aSrcP(dir, rowt));
    loadTile(bBuf0, bSrcP(dir, chunk, 0));
    cp_commit();
    int pb = 0;

    float c0[2][4][4], c1[2][4][4];
    float s_acc[4], bmax[4];
    #pragma unroll
    for (int q = 0; q < 4; q++) { s_acc[q] = 0.0f; bmax[q] = -2.0f; }

    for (;;) {
        int nu = u + 1;
        const bool more = nu < uEnd;
        int ndir = dir, nrowt = rowt, nchunk = chunk;
        if (more) {
            ndir = nu / 1280; int r2 = nu % 1280; nrowt = r2 / 40; nchunk = r2 % 40;
        }

        TILE_BODY(c0, c1, 0, 0,
            { loadTile(pb ? bBuf0 : bBuf1, bSrcP(dir, chunk, 1)); cp_commit(); })
        TILE_BODY(c1, c0, 1, 1,
            { loadTile(pb ? bBuf0 : bBuf1, bSrcP(dir, chunk, 2)); cp_commit(); })
        TILE_BODY(c0, c1, 2, 1,
            { loadTile(pb ? bBuf0 : bBuf1, bSrcP(dir, chunk, 3)); cp_commit(); })
        TILE_BODY(c1, c0, 3, 1,
            { if (more) { loadTile(pb ? bBuf0 : bBuf1, bSrcP(ndir, nchunk, 0)); cp_commit(); } })

        // Immediate epilogue of tile 3 (c1), then unit flush.
        {
            const int colg0 = chunk * 512 + 384;
            const int isB = colg0 >= NB;
            const int dg = (!isB) && (colg0 == rowt * 128);
            #pragma unroll
            for (int mf = 0; mf < 2; mf++) {
                #pragma unroll
                for (int nf = 0; nf < 4; nf++) {
                    #pragma unroll
                    for (int e = 0; e < 4; e++) {
                        float v = c1[mf][nf][e];
                        int ri = mf * 2 + (e >> 1);
                        s_acc[ri] += ex2f(fmaf(cl2, v, -cl2));
                        if (isB) {
                            bmax[ri] = fmaxf(bmax[ri], v);
                        } else if (dg) {
                            int row_l = wm * 32 + mf * 16 + (lane >> 2) + 8 * (e >> 1);
                            int col_l = wn * 32 + nf * 8 + 2 * (lane & 3) + (e & 1);
                            if (row_l == col_l) g_diag[dir][rowt * 128 + row_l] = scale * v;
                        }
                    }
                }
            }
        }
        // Unit flush: lane-quad shfl reduce, then merge 4 wn-groups via smem.
        #pragma unroll
        for (int q = 0; q < 4; q++) {
            float s = s_acc[q], m = bmax[q];
            s += __shfl_xor_sync(0xffffffffu, s, 1);
            s += __shfl_xor_sync(0xffffffffu, s, 2);
            m = fmaxf(m, __shfl_xor_sync(0xffffffffu, m, 1));
            m = fmaxf(m, __shfl_xor_sync(0xffffffffu, m, 2));
            if ((lane & 3) == 0) {
                int row_l = wm * 32 + (q >> 1) * 16 + (q & 1) * 8 + (lane >> 2);
                scrS[wn * 128 + row_l] = s;
                scrM[wn * 128 + row_l] = m;
            }
            s_acc[q] = 0.0f; bmax[q] = -2.0f;
        }
        __syncthreads();
        if (tid < TM) {
            float s = scrS[tid] + scrS[128 + tid] + scrS[256 + tid] + scrS[384 + tid];
            float m = fmaxf(fmaxf(scrM[tid], scrM[128 + tid]),
                            fmaxf(scrM[256 + tid], scrM[384 + tid]));
            g_s[dir][rowt * 128 + tid][chunk]    = s;
            g_bmax[dir][rowt * 128 + tid][chunk] = m;
        }
        if (more && (nrowt != rowt || ndir != dir)) {
            // Barrier above guarantees all warps finished this unit's MMAs.
            loadTile(aBase, aSrcP(ndir, nrowt));
            cp_commit();
        }
        if (!more) break;
        u = nu; dir = ndir; rowt = nrowt; chunk = nchunk;
    }
}

// ---------------------------------------------------------------------------
// krow: 32 blocks x 256 threads, one row each. Merge chunk partials, per-row
// CE (fast log) + ICEL, block reduce; LAST block folds the 32 partials.
// ---------------------------------------------------------------------------
__global__ void krow(const float* __restrict__ scale_ptr, float* __restrict__ out) {
    const float scale = *scale_ptr;
    const int tid = threadIdx.x;
    const int gid = blockIdx.x * 256 + tid;       // 0..8191
    const int dir = gid >> 12, row = gid & (NB - 1);

    float s = 0.0f;
    #pragma unroll
    for (int ch = 0; ch < NCH; ch++) s += g_s[dir][row][ch];
    float m = -2.0f;
    #pragma unroll
    for (int ch = 8; ch < NCH; ch++) m = fmaxf(m, g_bmax[dir][row][ch]);

    float nce = scale + __logf(s) - g_diag[dir][row];
    float sq = 0.0f, cn = 0.0f;
    if (m > 0.2f) { sq = 2.0f - 2.0f * m; cn = 1.0f; }
    float v[5];
    v[0] = nce;
    v[1] = dir == 0 ? sq : 0.0f;
    v[2] = dir == 0 ? cn : 0.0f;
    v[3] = dir == 1 ? sq : 0.0f;
    v[4] = dir == 1 ? cn : 0.0f;

    __shared__ float red[5][256];
    #pragma unroll
    for (int q = 0; q < 5; q++) red[q][tid] = v[q];
    __syncthreads();
    for (int o = 128; o > 0; o >>= 1) {
        if (tid < o) {
            #pragma unroll
            for (int q = 0; q < 5; q++) red[q][tid] += red[q][tid + o];
        }
        __syncthreads();
    }
    __shared__ int isLast;
    if (tid == 0) {
        #pragma unroll
        for (int q = 0; q < 5; q++) g_part[blockIdx.x][q] = red[q][0];
        __threadfence();
        isLast = (atomicAdd(&g_cnt, 1) == 31);
    }
    __syncthreads();
    if (isLast && tid < 32) {
        float w[5];
        #pragma unroll
        for (int q = 0; q < 5; q++) w[q] = g_part[tid][q];
        #pragma unroll
        for (int o = 16; o > 0; o >>= 1)
            #pragma unroll
            for (int q = 0; q < 5; q++) w[q] += __shfl_xor_sync(0xffffffffu, w[q], o);
        if (tid == 0) {
            float nceT = 0.5f * w[0] / (float)NB;
            float i1 = (w[2] > 0.0f) ? w[1] / (w[2] * (float)NC) : 0.0f;
            float i2 = (w[4] > 0.0f) ? w[3] / (w[4] * (float)NC) : 0.0f;
            out[0] = nceT + 0.5f * (0.5f * (i1 + i2));
            g_cnt = 0;   // reset for the next graph replay
        }
    }
}

// ---------------------------------------------------------------------------
extern "C" void kernel_launch(void* const* d_in, const int* in_sizes, int n_in,
                              void* d_out, int out_size) {
    const float* if1 = (const float*)d_in[0];
    const float* if2 = (const float*)d_in[1];
    const float* sc  = (const float*)d_in[2];
    const float* mb1 = (const float*)d_in[3];
    const float* mb2 = (const float*)d_in[4];
    float* out = (float*)d_out;

    int sms = 148;
    cudaDeviceGetAttribute(&sms, cudaDevAttrMultiProcessorCount, 0);
    if (sms <= 0) sms = 148;
    if (sms > NUNITS) sms = NUNITS;

    cudaFuncSetAttribute(kgemm, cudaFuncAttributeMaxDynamicSharedMemorySize, SMEM_DYN);

    int totalWarps = 2 * NB + 2 * NM;   // 40960 rows, one warp each
    kprep<<<totalWarps / 8, 256>>>(if1, if2, mb1, mb2);
    kgemm<<<sms, NTHREADS, SMEM_DYN>>>(sc);
    krow<<<32, 256>>>(sc, out);
}

// round 17
// speedup vs baseline: 1.5508x; 1.5508x over previous
#include <cuda_runtime.h>
#include <cuda_bf16.h>
#include <cstdint>
#include <math.h>

// Inputs: [0] if1 [4096,256] f32, [1] if2, [2] scale [1], [3] mb1 [16384,256] f32 (unit rows), [4] mb2
// Output: scalar f32.

namespace {
constexpr int NB = 4096, NC = 256, NM = 16384;
constexpr int TM = 128, TN = 128;
constexpr int ROWB = 512;             // bytes per K-major bf16 row
constexpr int TILEB = TM * ROWB;      // 64 KB
constexpr int NCH = 40;               // 512-col chunks over 20480
constexpr int NUNITS = 2 * 32 * NCH;  // 2560 uniform units of 4 tiles
constexpr int NTHREADS = 512;         // 16 warps, 4 per SMSP
constexpr int SMEM_DYN = 1024 + 3 * TILEB + 4096;  // pad + A + B0 + B1 + scratch
}

// Device-global scratch (no allocations allowed)
__device__ __nv_bfloat16 g_f1h[NB * NC];
__device__ __nv_bfloat16 g_f2h[NB * NC];
__device__ __nv_bfloat16 g_mb1h[NM * NC];
__device__ __nv_bfloat16 g_mb2h[NM * NC];
__device__ float g_s[2][NB][NCH];
__device__ float g_bmax[2][NB][NCH];
__device__ float g_diag[2][NB];
__device__ float g_part[32][8];       // per-block partials (5 used)
__device__ int   g_cnt;               // krow completion counter (self-resetting)

// ---------------- PTX helpers (plain sm_80+-class) ----------------
__device__ __forceinline__ uint32_t smem_u32(const void* p) {
    uint32_t a;
    asm("{ .reg .u64 t; cvta.to.shared.u64 t, %1; cvt.u32.u64 %0, t; }" : "=r"(a) : "l"(p));
    return a;
}
__device__ __forceinline__ void cp16(uint32_t d, const void* s) {
    asm volatile("cp.async.cg.shared.global [%0], [%1], 16;" :: "r"(d), "l"(s) : "memory");
}
__device__ __forceinline__ void cp_commit() { asm volatile("cp.async.commit_group;" ::: "memory"); }
__device__ __forceinline__ void cp_wait0()  { asm volatile("cp.async.wait_group 0;" ::: "memory"); }
__device__ __forceinline__ void ldsm4(uint32_t& r0, uint32_t& r1, uint32_t& r2, uint32_t& r3,
                                      uint32_t addr) {
    asm volatile("ldmatrix.sync.aligned.m8n8.x4.shared.b16 {%0,%1,%2,%3}, [%4];"
                 : "=r"(r0), "=r"(r1), "=r"(r2), "=r"(r3) : "r"(addr));
}
__device__ __forceinline__ void mma16816(float* c, const uint32_t* a, const uint32_t* b) {
    asm volatile(
        "mma.sync.aligned.m16n8k16.row.col.f32.bf16.bf16.f32 "
        "{%0,%1,%2,%3}, {%4,%5,%6,%7}, {%8,%9}, {%0,%1,%2,%3};"
        : "+f"(c[0]), "+f"(c[1]), "+f"(c[2]), "+f"(c[3])
        : "r"(a[0]), "r"(a[1]), "r"(a[2]), "r"(a[3]), "r"(b[0]), "r"(b[1]));
}
__device__ __forceinline__ float ex2f(float x) {
    float e; asm("ex2.approx.f32 %0, %1;" : "=f"(e) : "f"(x)); return e;
}

// ---------------------------------------------------------------------------
// Prep: normalize features -> bf16; convert banks -> bf16. One warp per row.
// (Measured near bandwidth-bound: 60 MB total traffic, ~86% of achievable.)
// ---------------------------------------------------------------------------
__global__ void kprep(const float* __restrict__ in1, const float* __restrict__ in2,
                      const float* __restrict__ b1, const float* __restrict__ b2) {
    int gw = (blockIdx.x * blockDim.x + threadIdx.x) >> 5;
    int lane = threadIdx.x & 31;
    const float* src; __nv_bfloat16* dst; bool donorm; int row;
    if (gw < NB)               { src = in1; dst = g_f1h;  row = gw;               donorm = true; }
    else if (gw < 2 * NB)      { src = in2; dst = g_f2h;  row = gw - NB;          donorm = true; }
    else if (gw < 2 * NB + NM) { src = b1;  dst = g_mb1h; row = gw - 2 * NB;      donorm = false; }
    else                       { src = b2;  dst = g_mb2h; row = gw - 2 * NB - NM; donorm = false; }

    const float4* s4 = (const float4*)(src + (size_t)row * NC);
    float4 v0 = s4[lane * 2], v1 = s4[lane * 2 + 1];
    float inv = 1.0f;
    if (donorm) {
        float ss = v0.x*v0.x + v0.y*v0.y + v0.z*v0.z + v0.w*v0.w
                 + v1.x*v1.x + v1.y*v1.y + v1.z*v1.z + v1.w*v1.w;
        #pragma unroll
        for (int o = 16; o > 0; o >>= 1) ss += __shfl_xor_sync(0xffffffffu, ss, o);
        inv = 1.0f / fmaxf(sqrtf(ss), 1e-12f);
    }
    __nv_bfloat162 p0 = __floats2bfloat162_rn(v0.x * inv, v0.y * inv);
    __nv_bfloat162 p1 = __floats2bfloat162_rn(v0.z * inv, v0.w * inv);
    __nv_bfloat162 p2 = __floats2bfloat162_rn(v1.x * inv, v1.y * inv);
    __nv_bfloat162 p3 = __floats2bfloat162_rn(v1.z * inv, v1.w * inv);
    uint4 o;
    o.x = *(uint32_t*)&p0; o.y = *(uint32_t*)&p1; o.z = *(uint32_t*)&p2; o.w = *(uint32_t*)&p3;
    ((uint4*)(dst + (size_t)row * NC))[lane] = o;
}

// ---------------------------------------------------------------------------
// Persistent fused GEMM (mma.sync bf16), 16 warps, warp tile 32x32.
// Unit = (dir, rowt, 512-col chunk) = 4 tiles. Static contiguous partition.
// Deferred epilogue via c0/c1 accumulator double-buffer: prev tile's
// exp-sum/max/diag interleaves with current tile's MMA loop (2 elems per ks).
// ---------------------------------------------------------------------------
#define TILE_BODY(CCUR, CPREV, TT, DOPREV, PREFETCH_STMT)                          \
  {                                                                                \
    cp_wait0(); __syncthreads();                                                   \
    PREFETCH_STMT                                                                  \
    _Pragma("unroll") for (int mf = 0; mf < 2; mf++)                               \
      _Pragma("unroll") for (int nf = 0; nf < 4; nf++)                             \
        _Pragma("unroll") for (int e = 0; e < 4; e++) CCUR[mf][nf][e] = 0.0f;      \
    const uint32_t bA0 = (pb ? bBuf1 : bBuf0) + (uint32_t)bRowL * ROWB;            \
    const uint32_t bA1 = bA0 + 16u * ROWB;                                         \
    const int pcolg0 = chunk * 512 + ((TT) - 1) * 128;                             \
    const int pBank = pcolg0 >= NB;                                                \
    const int pDiag = (!pBank) && (pcolg0 == rowt * 128);                          \
    _Pragma("unroll") for (int ks = 0; ks < 16; ks++) {                            \
      const uint32_t offA = ((uint32_t)(ks * 32) + aKsel) ^ sw;                    \
      const uint32_t offB = ((uint32_t)(ks * 32) + bKsel) ^ sw;                    \
      uint32_t a[2][4], b[4][2];                                                   \
      ldsm4(a[0][0], a[0][1], a[0][2], a[0][3], aAddr0 + offA);                    \
      ldsm4(a[1][0], a[1][1], a[1][2], a[1][3], aAddr1 + offA);                    \
      ldsm4(b[0][0], b[0][1], b[1][0], b[1][1], bA0 + offB);                       \
      ldsm4(b[2][0], b[2][1], b[3][0], b[3][1], bA1 + offB);                       \
      _Pragma("unroll") for (int mf = 0; mf < 2; mf++)                             \
        _Pragma("unroll") for (int nf = 0; nf < 4; nf++)                           \
          mma16816(CCUR[mf][nf], a[mf], b[nf]);                                    \
      if (DOPREV) {                                                                \
        const int mf = ks & 1, nf = (ks >> 1) & 3, eh = ks >> 3;                   \
        _Pragma("unroll") for (int e2 = 0; e2 < 2; e2++) {                         \
          const int e = eh * 2 + e2;                                               \
          float v = CPREV[mf][nf][e];                                              \
          int ri = mf * 2 + eh;                                                    \
          s_acc[ri] += ex2f(fmaf(cl2, v, -cl2));                                   \
          if (pBank) bmax[ri] = fmaxf(bmax[ri], v);                                \
          else if (pDiag) {                                                        \
            int row_l = wm * 32 + mf * 16 + (lane >> 2) + 8 * eh;                  \
            int col_l = wn * 32 + nf * 8 + 2 * (lane & 3) + e2;                    \
            if (row_l == col_l) g_diag[dir][rowt * 128 + row_l] = scale * v;       \
          }                                                                        \
        }                                                                          \
      }                                                                            \
    }                                                                              \
    pb ^= 1;                                                                       \
  }

__global__ void __launch_bounds__(NTHREADS, 1) kgemm(const float* __restrict__ scale_ptr) {
    extern __shared__ char dsm[];
    const uint32_t raw  = smem_u32(dsm);
    const uint32_t base = (raw + 1023u) & ~1023u;
    const uint32_t aBase = base;
    const uint32_t bBuf0 = base + TILEB;
    const uint32_t bBuf1 = base + 2 * TILEB;
    float* scrS = (float*)(dsm + (base - raw) + 3 * TILEB);
    float* scrM = scrS + 512;

    const int tid = threadIdx.x, wid = tid >> 5, lane = tid & 31;
    const int wm = wid & 3, wn = wid >> 2;        // 4x4 warp grid, 32x32 tiles
    const float scale = *scale_ptr;
    const float cl2 = scale * 1.4426950408889634f;

    const int G = gridDim.x;
    int uBeg = (int)((long long)blockIdx.x * NUNITS / G);
    int uEnd = (int)((long long)(blockIdx.x + 1) * NUNITS / G);
    if (uBeg >= uEnd) return;

    const int r8 = lane & 7;
    const uint32_t sw = (uint32_t)(r8 << 4);
    const int aRowL = wm * 32 + r8 + ((lane >> 3) & 1) * 8;
    const uint32_t aKsel = (uint32_t)(((lane >> 4) & 1) * 16);
    const int bRowL = wn * 32 + r8 + ((lane >> 4) & 1) * 8;
    const uint32_t bKsel = (uint32_t)(((lane >> 3) & 1) * 16);
    const uint32_t aAddr0 = aBase + (uint32_t)aRowL * ROWB;
    const uint32_t aAddr1 = aAddr0 + 16u * ROWB;

    auto loadTile = [&](uint32_t sb, const char* src) {
        #pragma unroll
        for (int it = 0; it < 8; it++) {
            int idx = tid + it * NTHREADS;
            int r   = idx >> 5;
            uint32_t kb = (uint32_t)((idx & 31) * 16);
            cp16(sb + (uint32_t)r * ROWB + (kb ^ (uint32_t)((r & 7) << 4)),
                 src + (size_t)r * ROWB + kb);
        }
    };
    auto aSrcP = [&](int d, int rt) -> const char* {
        return (const char*)((d ? g_f2h : g_f1h) + (size_t)rt * TM * NC);
    };
    auto bSrcP = [&](int d, int ch, int t) -> const char* {
        int colg0 = ch * 512 + t * 128;
        const __nv_bfloat16* p = (colg0 < NB)
            ? (d ? g_f1h : g_f2h) + (size_t)colg0 * NC
            : (d ? g_mb1h : g_mb2h) + (size_t)(colg0 - NB) * NC;
        return (const char*)p;
    };

    int u = uBeg;
    int dir = u / 1280, rem = u % 1280, rowt = rem / 40, chunk = rem % 40;
    loadTile(aBase, aSrcP(dir, rowt));
    loadTile(bBuf0, bSrcP(dir, chunk, 0));
    cp_commit();
    int pb = 0;

    float c0[2][4][4], c1[2][4][4];
    float s_acc[4], bmax[4];
    #pragma unroll
    for (int q = 0; q < 4; q++) { s_acc[q] = 0.0f; bmax[q] = -2.0f; }

    for (;;) {
        int nu = u + 1;
        const bool more = nu < uEnd;
        int ndir = dir, nrowt = rowt, nchunk = chunk;
        if (more) {
            ndir = nu / 1280; int r2 = nu % 1280; nrowt = r2 / 40; nchunk = r2 % 40;
        }

        TILE_BODY(c0, c1, 0, 0,
            { loadTile(pb ? bBuf0 : bBuf1, bSrcP(dir, chunk, 1)); cp_commit(); })
        TILE_BODY(c1, c0, 1, 1,
            { loadTile(pb ? bBuf0 : bBuf1, bSrcP(dir, chunk, 2)); cp_commit(); })
        TILE_BODY(c0, c1, 2, 1,
            { loadTile(pb ? bBuf0 : bBuf1, bSrcP(dir, chunk, 3)); cp_commit(); })
        TILE_BODY(c1, c0, 3, 1,
            { if (more) { loadTile(pb ? bBuf0 : bBuf1, bSrcP(ndir, nchunk, 0)); cp_commit(); } })

        // Immediate epilogue of tile 3 (c1), then unit flush.
        {
            const int colg0 = chunk * 512 + 384;
            const int isB = colg0 >= NB;
            const int dg = (!isB) && (colg0 == rowt * 128);
            #pragma unroll
            for (int mf = 0; mf < 2; mf++) {
                #pragma unroll
                for (int nf = 0; nf < 4; nf++) {
                    #pragma unroll
                    for (int e = 0; e < 4; e++) {
                        float v = c1[mf][nf][e];
                        int ri = mf * 2 + (e >> 1);
                        s_acc[ri] += ex2f(fmaf(cl2, v, -cl2));
                        if (isB) {
                            bmax[ri] = fmaxf(bmax[ri], v);
                        } else if (dg) {
                            int row_l = wm * 32 + mf * 16 + (lane >> 2) + 8 * (e >> 1);
                            int col_l = wn * 32 + nf * 8 + 2 * (lane & 3) + (e & 1);
                            if (row_l == col_l) g_diag[dir][rowt * 128 + row_l] = scale * v;
                        }
                    }
                }
            }
        }
        // Unit flush: lane-quad shfl reduce, then merge 4 wn-groups via smem.
        #pragma unroll
        for (int q = 0; q < 4; q++) {
            float s = s_acc[q], m = bmax[q];
            s += __shfl_xor_sync(0xffffffffu, s, 1);
            s += __shfl_xor_sync(0xffffffffu, s, 2);
            m = fmaxf(m, __shfl_xor_sync(0xffffffffu, m, 1));
            m = fmaxf(m, __shfl_xor_sync(0xffffffffu, m, 2));
            if ((lane & 3) == 0) {
                int row_l = wm * 32 + (q >> 1) * 16 + (q & 1) * 8 + (lane >> 2);
                scrS[wn * 128 + row_l] = s;
                scrM[wn * 128 + row_l] = m;
            }
            s_acc[q] = 0.0f; bmax[q] = -2.0f;
        }
        __syncthreads();
        if (tid < TM) {
            float s = scrS[tid] + scrS[128 + tid] + scrS[256 + tid] + scrS[384 + tid];
            float m = fmaxf(fmaxf(scrM[tid], scrM[128 + tid]),
                            fmaxf(scrM[256 + tid], scrM[384 + tid]));
            g_s[dir][rowt * 128 + tid][chunk]    = s;
            g_bmax[dir][rowt * 128 + tid][chunk] = m;
        }
        if (more && (nrowt != rowt || ndir != dir)) {
            // Barrier above guarantees all warps finished this unit's MMAs.
            loadTile(aBase, aSrcP(ndir, nrowt));
            cp_commit();
        }
        if (!more) break;
        u = nu; dir = ndir; rowt = nrowt; chunk = nchunk;
    }
}

// ---------------------------------------------------------------------------
// krow: 32 blocks x 256 threads, one row each. Merge chunk partials, per-row
// CE (fast log) + ICEL, block reduce; LAST block folds the 32 partials.
// ---------------------------------------------------------------------------
__global__ void krow(const float* __restrict__ scale_ptr, float* __restrict__ out) {
    const float scale = *scale_ptr;
    const int tid = threadIdx.x;
    const int gid = blockIdx.x * 256 + tid;       // 0..8191
    const int dir = gid >> 12, row = gid & (NB - 1);

    float s = 0.0f;
    #pragma unroll
    for (int ch = 0; ch < NCH; ch++) s += g_s[dir][row][ch];
    float m = -2.0f;
    #pragma unroll
    for (int ch = 8; ch < NCH; ch++) m = fmaxf(m, g_bmax[dir][row][ch]);

    float nce = scale + __logf(s) - g_diag[dir][row];
    float sq = 0.0f, cn = 0.0f;
    if (m > 0.2f) { sq = 2.0f - 2.0f * m; cn = 1.0f; }
    float v[5];
    v[0] = nce;
    v[1] = dir == 0 ? sq : 0.0f;
    v[2] = dir == 0 ? cn : 0.0f;
    v[3] = dir == 1 ? sq : 0.0f;
    v[4] = dir == 1 ? cn : 0.0f;

    __shared__ float red[5][256];
    #pragma unroll
    for (int q = 0; q < 5; q++) red[q][tid] = v[q];
    __syncthreads();
    for (int o = 128; o > 0; o >>= 1) {
        if (tid < o) {
            #pragma unroll
            for (int q = 0; q < 5; q++) red[q][tid] += red[q][tid + o];
        }
        __syncthreads();
    }
    __shared__ int isLast;
    if (tid == 0) {
        #pragma unroll
        for (int q = 0; q < 5; q++) g_part[blockIdx.x][q] = red[q][0];
        __threadfence();
        isLast = (atomicAdd(&g_cnt, 1) == 31);
    }
    __syncthreads();
    if (isLast && tid < 32) {
        float w[5];
        #pragma unroll
        for (int q = 0; q < 5; q++) w[q] = g_part[tid][q];
        #pragma unroll
        for (int o = 16; o > 0; o >>= 1)
            #pragma unroll
            for (int q = 0; q < 5; q++) w[q] += __shfl_xor_sync(0xffffffffu, w[q], o);
        if (tid == 0) {
            float nceT = 0.5f * w[0] / (float)NB;
            float i1 = (w[2] > 0.0f) ? w[1] / (w[2] * (float)NC) : 0.0f;
            float i2 = (w[4] > 0.0f) ? w[3] / (w[4] * (float)NC) : 0.0f;
            out[0] = nceT + 0.5f * (0.5f * (i1 + i2));
            g_cnt = 0;   // reset for the next graph replay
        }
    }
}

// ---------------------------------------------------------------------------
extern "C" void kernel_launch(void* const* d_in, const int* in_sizes, int n_in,
                              void* d_out, int out_size) {
    const float* if1 = (const float*)d_in[0];
    const float* if2 = (const float*)d_in[1];
    const float* sc  = (const float*)d_in[2];
    const float* mb1 = (const float*)d_in[3];
    const float* mb2 = (const float*)d_in[4];
    float* out = (float*)d_out;

    int sms = 148;
    cudaDeviceGetAttribute(&sms, cudaDevAttrMultiProcessorCount, 0);
    if (sms <= 0) sms = 148;
    if (sms > NUNITS) sms = NUNITS;

    cudaFuncSetAttribute(kgemm, cudaFuncAttributeMaxDynamicSharedMemorySize, SMEM_DYN);

    int totalWarps = 2 * NB + 2 * NM;   // 40960 rows, one warp each
    kprep<<<totalWarps / 8, 256>>>(if1, if2, mb1, mb2);
    kgemm<<<sms, NTHREADS, SMEM_DYN>>>(sc);
    krow<<<32, 256>>>(sc, out);
}